// round 8
// baseline (speedup 1.0000x reference)
#include <cuda_runtime.h>
#include <cuda_bf16.h>

// SoftPerspectiveShader: fused sample_textures + softmax_rgb_blend
// R7: occupancy push. DRAM-busy time is pinned at ~28us across all prior
// rounds; all variation is latency-idle gap. 40 warps/SM x 6 outstanding
// LDG.128 under-covers DRAM latency. Force 6 blocks/SM (48 warps) via
// __launch_bounds__(256,6) (<=42 regs). To fit: two-pass weight compute
// (pass1 -> keep/zmax keeping zinv[8]; pass2 recomputes sigmoid, 1 MUFU
// each — MUFU is nowhere near binding). Otherwise EXACT R1 structure:
// front-batched vector loads, one if(w>0) branch region per k with
// in-branch scalar gathers (92% of pixels take exactly one), no pad
// kernel, no prefetch, no select-chain extras.

#define SIGMA_INV 1e4f
#define GAMMA_INV 1e4f
#define ZFAR_F    100.0f
#define ZRANGE_F  99.0f
#define EPS_F     1e-10f

__global__ __launch_bounds__(256, 6) void soft_shader_kernel(
    const int4*   __restrict__ p2f,    // [P][2] int4  (K=8)
    const float*  __restrict__ bary,   // [P][8][3]
    const float4* __restrict__ zbuf,   // [P][2] float4
    const float4* __restrict__ dists,  // [P][2] float4
    const float*  __restrict__ fcol,   // [F][3][3]
    float4*       __restrict__ out,    // [P]
    int P)
{
    int p = blockIdx.x * blockDim.x + threadIdx.x;
    if (p >= P) return;

    // ---- all six streaming LDG.128 issue back-to-back (MLP_p1 = 6) ----
    const int4   fa = p2f[2 * p],   fb = p2f[2 * p + 1];
    const float4 za = zbuf[2 * p],  zb = zbuf[2 * p + 1];
    const float4 da = dists[2 * p], db = dists[2 * p + 1];

    int   faces[8] = {fa.x, fa.y, fa.z, fa.w, fb.x, fb.y, fb.z, fb.w};
    float zv[8]    = {za.x, za.y, za.z, za.w, zb.x, zb.y, zb.z, zb.w};
    float dv[8]    = {da.x, da.y, da.z, da.w, db.x, db.y, db.z, db.w};

    // ---- pass 1: alpha product and z_inv_max (consumes z, keeps zinv) ----
    float zinv[8];
    float zmax = EPS_F;
    float keep = 1.0f;
#pragma unroll
    for (int k = 0; k < 8; k++) {
        bool  m  = faces[k] >= 0;
        float e  = __expf(dv[k] * SIGMA_INV);          // exp(d/sigma)
        float pr = m ? __fdividef(1.0f, 1.0f + e) : 0.0f;
        keep *= (1.0f - pr);
        float zi = m ? ((ZFAR_F - zv[k]) / ZRANGE_F) : 0.0f;  // true div (matches ref)
        zinv[k] = zi;
        zmax = fmaxf(zmax, zi);
    }

    float delta = fmaxf(__expf((EPS_F - zmax) * GAMMA_INV), EPS_F);
    float denom = delta;
    float r = 0.0f, g = 0.0f, b = 0.0f;

    // ---- pass 2: weights + gathers (sigmoid recomputed: 1 MUFU) ----
#pragma unroll
    for (int k = 0; k < 8; k++) {
        bool  m  = faces[k] >= 0;
        float e  = __expf(dv[k] * SIGMA_INV);
        float pr = m ? __fdividef(1.0f, 1.0f + e) : 0.0f;
        float w  = pr * __expf((zinv[k] - zmax) * GAMMA_INV);  // exp(0)=1 at argmax
        denom += w;
        if (w > 0.0f) {
            const float* bc = bary + (size_t)p * 24 + (size_t)k * 3;
            float b0 = bc[0], b1 = bc[1], b2 = bc[2];
            const float* fc = fcol + (size_t)faces[k] * 9;
            float t0 = b0 * fc[0] + b1 * fc[3] + b2 * fc[6];
            float t1 = b0 * fc[1] + b1 * fc[4] + b2 * fc[7];
            float t2 = b0 * fc[2] + b1 * fc[5] + b2 * fc[8];
            r += w * t0; g += w * t1; b += w * t2;
        }
    }

    float inv = __fdividef(1.0f, denom);
    float4 o;
    o.x = (r + delta) * inv;   // background = (1,1,1)
    o.y = (g + delta) * inv;
    o.z = (b + delta) * inv;
    o.w = keep;                // 1 - alpha
    out[p] = o;
}

extern "C" void kernel_launch(void* const* d_in, const int* in_sizes, int n_in,
                              void* d_out, int out_size) {
    const int*   p2f   = (const int*)d_in[0];
    const float* bary  = (const float*)d_in[1];
    const float* zbufp = (const float*)d_in[2];
    const float* dist  = (const float*)d_in[3];
    const float* fcol  = (const float*)d_in[4];
    int P = in_sizes[0] / 8;   // N*H*W pixels

    int threads = 256;
    int blocks  = (P + threads - 1) / threads;
    soft_shader_kernel<<<blocks, threads>>>(
        (const int4*)p2f, bary, (const float4*)zbufp, (const float4*)dist,
        fcol, (float4*)d_out, P);
}